// round 3
// baseline (speedup 1.0000x reference)
#include <cuda_runtime.h>

#define N_NODES 100000
#define N_EDGES 1600000
#define C       128
#define NCLS    16
#define DCAT    512   // 128 + 3*128

// ---- scratch (device globals: no allocation allowed) ----
__device__ float g_tmp[(size_t)N_NODES * C];   // x_prev @ W  (51.2 MB)
__device__ float g_dis[N_NODES];               // rsqrt(degree)
__device__ int   g_cnt[N_NODES];               // in-degree counts
__device__ int   g_rowstart[N_NODES + 1];      // CSR row offsets
__device__ int   g_cursor[N_NODES];            // fill cursors
__device__ int   g_csr_src[N_EDGES];           // CSR: src node per slot
__device__ float g_csr_w[N_EDGES];             // CSR: dis[src] per slot

// ---------------------------------------------------------------------------
// K0: copy x into h[:,0:128] (stride 512); zero degree counters.
// ---------------------------------------------------------------------------
__global__ void k_init(const float* __restrict__ x, float* __restrict__ h) {
    int t = blockIdx.x * blockDim.x + threadIdx.x;
    if (t >= N_NODES * 32) return;
    int node = t >> 5;
    int lane = t & 31;
    float4 v = ((const float4*)(x + (size_t)node * C))[lane];
    ((float4*)(h + (size_t)node * DCAT))[lane] = v;
    if (lane == 0) g_cnt[node] = 0;
}

// K1: in-degree count.  edge_index is INT32 (JAX x64 disabled): row0 = src
// (first N_EDGES ints), row1 = dst (next N_EDGES ints).
__global__ void k_deg(const int* __restrict__ ei) {
    int e = blockIdx.x * blockDim.x + threadIdx.x;
    if (e >= N_EDGES) return;
    int d = ei[N_EDGES + e];
    atomicAdd(&g_cnt[d], 1);
}

// K2: single-block exclusive scan of g_cnt -> g_rowstart / g_cursor
__global__ void k_scan() {
    __shared__ int buf[1024];
    __shared__ int carry;
    int tid = threadIdx.x;
    if (tid == 0) carry = 0;
    __syncthreads();
    for (int base = 0; base < N_NODES; base += 1024) {
        int i = base + tid;
        int v = (i < N_NODES) ? g_cnt[i] : 0;
        buf[tid] = v;
        __syncthreads();
        for (int off = 1; off < 1024; off <<= 1) {
            int t = (tid >= off) ? buf[tid - off] : 0;
            __syncthreads();
            buf[tid] += t;
            __syncthreads();
        }
        int incl = buf[tid];
        int oldc = carry;
        if (i < N_NODES) {
            int excl = oldc + incl - v;
            g_rowstart[i] = excl;
            g_cursor[i]   = excl;
        }
        __syncthreads();
        if (tid == 1023) carry = oldc + incl;
        __syncthreads();
    }
    if (threadIdx.x == 0) g_rowstart[N_NODES] = carry;
}

// K3: dis = rsqrt(indeg + 1)   (+1 = self loop)
__global__ void k_rsqrt() {
    int i = blockIdx.x * blockDim.x + threadIdx.x;
    if (i < N_NODES) g_dis[i] = rsqrtf((float)(g_cnt[i] + 1));
}

// K4: bucket-fill CSR: slot per (dst, incoming edge); store src and dis[src]
__global__ void k_fill(const int* __restrict__ ei) {
    int e = blockIdx.x * blockDim.x + threadIdx.x;
    if (e >= N_EDGES) return;
    int s = ei[e];
    int d = ei[N_EDGES + e];
    int pos = atomicAdd(&g_cursor[d], 1);
    g_csr_src[pos] = s;
    g_csr_w[pos]   = g_dis[s];
}

// ---------------------------------------------------------------------------
// GEMM: g_tmp[N,128] = in[N, stride DCAT] @ W[128,128]
// block = 128 threads (one per output column), 16 rows per block.
// ---------------------------------------------------------------------------
#define GR 16
__global__ void k_gemm(const float* __restrict__ in, const float* __restrict__ W) {
    __shared__ float xs[GR][132];
    __shared__ float ws[32][C];
    int c = threadIdx.x;                 // 0..127
    int row0 = blockIdx.x * GR;

#pragma unroll
    for (int r = 0; r < GR; ++r)
        xs[r][c] = in[(size_t)(row0 + r) * DCAT + c];

    float acc[GR];
#pragma unroll
    for (int r = 0; r < GR; ++r) acc[r] = 0.0f;

    for (int k0 = 0; k0 < C; k0 += 32) {
        __syncthreads();
#pragma unroll
        for (int j = 0; j < 32; ++j)
            ws[j][c] = W[(k0 + j) * C + c];
        __syncthreads();
#pragma unroll
        for (int kk = 0; kk < 32; kk += 4) {
            float w0 = ws[kk + 0][c];
            float w1 = ws[kk + 1][c];
            float w2 = ws[kk + 2][c];
            float w3 = ws[kk + 3][c];
#pragma unroll
            for (int r = 0; r < GR; ++r) {
                float4 xv = *(const float4*)&xs[r][k0 + kk];
                acc[r] = fmaf(xv.x, w0,
                         fmaf(xv.y, w1,
                         fmaf(xv.z, w2,
                         fmaf(xv.w, w3, acc[r]))));
            }
        }
    }
#pragma unroll
    for (int r = 0; r < GR; ++r)
        g_tmp[(size_t)(row0 + r) * C + c] = acc[r];
}

// ---------------------------------------------------------------------------
// Aggregation: one warp per node.  out[d] = dis[d] * sum_{s in in(d)}
// dis[s]*tmp[s]  +  dis[d]^2 * tmp[d]  +  b.   Plain stores, no atomics.
// ---------------------------------------------------------------------------
__global__ void k_aggr(const float* __restrict__ b, float* __restrict__ out) {
    int warp = (blockIdx.x * blockDim.x + threadIdx.x) >> 5;
    int lane = threadIdx.x & 31;
    if (warp >= N_NODES) return;

    int rs = g_rowstart[warp];
    int re = g_rowstart[warp + 1];
    float4 acc = make_float4(0.f, 0.f, 0.f, 0.f);

#pragma unroll 4
    for (int e = rs; e < re; ++e) {
        int   s = g_csr_src[e];          // broadcast across warp
        float w = g_csr_w[e];
        float4 v = ((const float4*)(g_tmp + (size_t)s * C))[lane];
        acc.x = fmaf(v.x, w, acc.x);
        acc.y = fmaf(v.y, w, acc.y);
        acc.z = fmaf(v.z, w, acc.z);
        acc.w = fmaf(v.w, w, acc.w);
    }

    float di = g_dis[warp];
    float d2 = di * di;
    float4 sv = ((const float4*)(g_tmp + (size_t)warp * C))[lane];
    float4 bb = ((const float4*)b)[lane];
    float4 o;
    o.x = fmaf(acc.x, di, fmaf(sv.x, d2, bb.x));
    o.y = fmaf(acc.y, di, fmaf(sv.y, d2, bb.y));
    o.z = fmaf(acc.z, di, fmaf(sv.z, d2, bb.z));
    o.w = fmaf(acc.w, di, fmaf(sv.w, d2, bb.w));
    ((float4*)(out + (size_t)warp * DCAT))[lane] = o;
}

// ---------------------------------------------------------------------------
// Final linear: labels[N,16] = h[N,512] @ W_lin[512,16] + b_lin
// ---------------------------------------------------------------------------
__global__ void k_lin(const float* __restrict__ h, const float* __restrict__ Wl,
                      const float* __restrict__ bl, float* __restrict__ out) {
    __shared__ float ws[DCAT * 17];
    __shared__ float bs[NCLS];
    for (int idx = threadIdx.x; idx < DCAT * NCLS; idx += blockDim.x) {
        int c = idx >> 4;
        int k = idx & 15;
        ws[c * 17 + k] = Wl[idx];
    }
    if (threadIdx.x < NCLS) bs[threadIdx.x] = bl[threadIdx.x];
    __syncthreads();

    int warp = threadIdx.x >> 5;
    int lane = threadIdx.x & 31;
    int warpsPerGrid = (blockDim.x >> 5) * gridDim.x;
    for (int node = blockIdx.x * (blockDim.x >> 5) + warp; node < N_NODES;
         node += warpsPerGrid) {
        float acc[NCLS];
#pragma unroll
        for (int k = 0; k < NCLS; ++k) acc[k] = 0.0f;
        const float* hr = h + (size_t)node * DCAT;
#pragma unroll
        for (int j = 0; j < DCAT / 32; ++j) {
            int cidx = lane + 32 * j;
            float hv = hr[cidx];
            const float* wrow = &ws[cidx * 17];
#pragma unroll
            for (int k = 0; k < NCLS; ++k)
                acc[k] = fmaf(hv, wrow[k], acc[k]);
        }
#pragma unroll
        for (int off = 16; off > 0; off >>= 1) {
#pragma unroll
            for (int k = 0; k < NCLS; ++k)
                acc[k] += __shfl_xor_sync(0xffffffffu, acc[k], off);
        }
        if (lane == 0) {
            float* op = out + (size_t)node * NCLS;
#pragma unroll
            for (int k = 0; k < NCLS; ++k) op[k] = acc[k] + bs[k];
        }
    }
}

// ---------------------------------------------------------------------------
extern "C" void kernel_launch(void* const* d_in, const int* in_sizes, int n_in,
                              void* d_out, int out_size) {
    const float* x     = (const float*)d_in[0];
    const int*   ei    = (const int*)d_in[1];      // int32! (JAX x64 off)
    const float* W[3]  = {(const float*)d_in[2], (const float*)d_in[4],
                          (const float*)d_in[6]};
    const float* b[3]  = {(const float*)d_in[3], (const float*)d_in[5],
                          (const float*)d_in[7]};
    const float* W_lin = (const float*)d_in[8];
    const float* b_lin = (const float*)d_in[9];

    float* labels = (float*)d_out;                      // [N, 16]
    float* h      = labels + (size_t)N_NODES * NCLS;    // [N, 512]

    const int TB = 256;
    k_init <<<(N_NODES * 32 + TB - 1) / TB, TB>>>(x, h);
    k_deg  <<<(N_EDGES + TB - 1) / TB, TB>>>(ei);
    k_scan <<<1, 1024>>>();
    k_rsqrt<<<(N_NODES + TB - 1) / TB, TB>>>();
    k_fill <<<(N_EDGES + TB - 1) / TB, TB>>>(ei);

    for (int l = 0; l < 3; ++l) {
        const float* in  = h + l * C;          // stride DCAT
        float*       out = h + (l + 1) * C;    // stride DCAT
        k_gemm<<<N_NODES / GR, 128>>>(in, W[l]);
        k_aggr<<<(N_NODES * 32 + TB - 1) / TB, TB>>>(b[l], out);
    }

    k_lin<<<2048, 256>>>(h, W_lin, b_lin, labels);
}

// round 4
// speedup vs baseline: 1.0995x; 1.0995x over previous
#include <cuda_runtime.h>

#define N_NODES 100000
#define N_EDGES 1600000
#define C       128
#define NCLS    16
#define DCAT    512   // 128 + 3*128

// ---- scratch (device globals: no allocation allowed) ----
__device__ float g_tmp[(size_t)N_NODES * C];   // x_prev @ W  (51.2 MB)
__device__ float g_dis[N_NODES];               // rsqrt(degree)
__device__ int   g_cnt[N_NODES];               // in-degree counts
__device__ int   g_rowstart[N_NODES + 1];      // CSR row offsets
__device__ int   g_cursor[N_NODES];            // fill cursors
__device__ int   g_csr_src[N_EDGES];           // CSR: src node per slot
__device__ float g_csr_w[N_EDGES];             // CSR: dis[src] per slot

// ---------------------------------------------------------------------------
// K0: copy x into h[:,0:128] (stride 512); zero degree counters.
// ---------------------------------------------------------------------------
__global__ void k_init(const float* __restrict__ x, float* __restrict__ h) {
    int t = blockIdx.x * blockDim.x + threadIdx.x;
    if (t >= N_NODES * 32) return;
    int node = t >> 5;
    int lane = t & 31;
    float4 v = ((const float4*)(x + (size_t)node * C))[lane];
    ((float4*)(h + (size_t)node * DCAT))[lane] = v;
    if (lane == 0) g_cnt[node] = 0;
}

// K1: in-degree count. edge_index is int32: row0 = src, row1 = dst.
__global__ void k_deg(const int* __restrict__ ei) {
    int e = blockIdx.x * blockDim.x + threadIdx.x;
    if (e >= N_EDGES) return;
    int d = ei[N_EDGES + e];
    atomicAdd(&g_cnt[d], 1);
}

// K2: single-block exclusive scan of g_cnt -> g_rowstart / g_cursor
__global__ void k_scan() {
    __shared__ int buf[1024];
    __shared__ int carry;
    int tid = threadIdx.x;
    if (tid == 0) carry = 0;
    __syncthreads();
    for (int base = 0; base < N_NODES; base += 1024) {
        int i = base + tid;
        int v = (i < N_NODES) ? g_cnt[i] : 0;
        buf[tid] = v;
        __syncthreads();
        for (int off = 1; off < 1024; off <<= 1) {
            int t = (tid >= off) ? buf[tid - off] : 0;
            __syncthreads();
            buf[tid] += t;
            __syncthreads();
        }
        int incl = buf[tid];
        int oldc = carry;
        if (i < N_NODES) {
            int excl = oldc + incl - v;
            g_rowstart[i] = excl;
            g_cursor[i]   = excl;
        }
        __syncthreads();
        if (tid == 1023) carry = oldc + incl;
        __syncthreads();
    }
    if (threadIdx.x == 0) g_rowstart[N_NODES] = carry;
}

// K3: dis = rsqrt(indeg + 1)   (+1 = self loop)
__global__ void k_rsqrt() {
    int i = blockIdx.x * blockDim.x + threadIdx.x;
    if (i < N_NODES) g_dis[i] = rsqrtf((float)(g_cnt[i] + 1));
}

// K4: bucket-fill CSR
__global__ void k_fill(const int* __restrict__ ei) {
    int e = blockIdx.x * blockDim.x + threadIdx.x;
    if (e >= N_EDGES) return;
    int s = ei[e];
    int d = ei[N_EDGES + e];
    int pos = atomicAdd(&g_cursor[d], 1);
    g_csr_src[pos] = s;
    g_csr_w[pos]   = g_dis[s];
}

// ---------------------------------------------------------------------------
// GEMM (register-tiled): g_tmp[N,128] = in[N, stride DCAT] @ W[128,128]
// 256 threads, block tile 128 rows x 128 cols, thread tile 8x8.
// K chunked by 8; smem transposed x tile + W tile; outer-product FMAs.
// ---------------------------------------------------------------------------
#define GK 8
__global__ void __launch_bounds__(256, 2)
k_gemm(const float* __restrict__ in, const float* __restrict__ W) {
    __shared__ float xs[GK][132];     // [k][row], padded
    __shared__ float ws[GK][128];     // [k][col]

    int tid  = threadIdx.x;
    int tc   = tid & 15;              // col group 0..15
    int tr   = tid >> 4;              // row group 0..15
    int row0 = blockIdx.x * 128;

    // load indices for x tile: each thread one float4 (row, 4 k's)
    int lrow = tid >> 1;              // 0..127
    int lkq  = (tid & 1) * 4;         // 0 or 4
    int grow = row0 + lrow;
    if (grow >= N_NODES) grow = N_NODES - 1;   // clamp (stores guarded)
    const float* xrow = in + (size_t)grow * DCAT;

    // load indices for W tile: thread -> (k = tid>>5, col4 = (tid&31)*4)
    int wk = tid >> 5;                // 0..7
    int wc = (tid & 31) * 4;

    float acc[8][8];
#pragma unroll
    for (int i = 0; i < 8; ++i)
#pragma unroll
        for (int j = 0; j < 8; ++j) acc[i][j] = 0.0f;

    for (int k0 = 0; k0 < C; k0 += GK) {
        // stage x tile (transposed) and W tile
        float4 xv = *(const float4*)(xrow + k0 + lkq);
        float4 wv = *(const float4*)(W + (k0 + wk) * C + wc);
        __syncthreads();              // previous chunk fully consumed
        xs[lkq + 0][lrow] = xv.x;
        xs[lkq + 1][lrow] = xv.y;
        xs[lkq + 2][lrow] = xv.z;
        xs[lkq + 3][lrow] = xv.w;
        *(float4*)&ws[wk][wc] = wv;
        __syncthreads();

#pragma unroll
        for (int k = 0; k < GK; ++k) {
            float4 a0 = *(const float4*)&xs[k][tr * 8];
            float4 a1 = *(const float4*)&xs[k][tr * 8 + 4];
            float4 b0 = *(const float4*)&ws[k][tc * 8];
            float4 b1 = *(const float4*)&ws[k][tc * 8 + 4];
            float a[8] = {a0.x, a0.y, a0.z, a0.w, a1.x, a1.y, a1.z, a1.w};
            float b[8] = {b0.x, b0.y, b0.z, b0.w, b1.x, b1.y, b1.z, b1.w};
#pragma unroll
            for (int i = 0; i < 8; ++i)
#pragma unroll
                for (int j = 0; j < 8; ++j)
                    acc[i][j] = fmaf(a[i], b[j], acc[i][j]);
        }
    }

    // store 8x8 tile
#pragma unroll
    for (int i = 0; i < 8; ++i) {
        int row = row0 + tr * 8 + i;
        if (row < N_NODES) {
            float4 o0 = make_float4(acc[i][0], acc[i][1], acc[i][2], acc[i][3]);
            float4 o1 = make_float4(acc[i][4], acc[i][5], acc[i][6], acc[i][7]);
            *(float4*)(g_tmp + (size_t)row * C + tc * 8)     = o0;
            *(float4*)(g_tmp + (size_t)row * C + tc * 8 + 4) = o1;
        }
    }
}

// ---------------------------------------------------------------------------
// Aggregation: one warp per node; gather-only, no atomics.
// out[d] = dis[d]*sum(dis[s]*tmp[s]) + dis[d]^2*tmp[d] + b
// ---------------------------------------------------------------------------
__global__ void k_aggr(const float* __restrict__ b, float* __restrict__ out) {
    int warp = (blockIdx.x * blockDim.x + threadIdx.x) >> 5;
    int lane = threadIdx.x & 31;
    if (warp >= N_NODES) return;

    int rs = g_rowstart[warp];
    int re = g_rowstart[warp + 1];
    float4 acc = make_float4(0.f, 0.f, 0.f, 0.f);

#pragma unroll 4
    for (int e = rs; e < re; ++e) {
        int   s = g_csr_src[e];
        float w = g_csr_w[e];
        float4 v = ((const float4*)(g_tmp + (size_t)s * C))[lane];
        acc.x = fmaf(v.x, w, acc.x);
        acc.y = fmaf(v.y, w, acc.y);
        acc.z = fmaf(v.z, w, acc.z);
        acc.w = fmaf(v.w, w, acc.w);
    }

    float di = g_dis[warp];
    float d2 = di * di;
    float4 sv = ((const float4*)(g_tmp + (size_t)warp * C))[lane];
    float4 bb = ((const float4*)b)[lane];
    float4 o;
    o.x = fmaf(acc.x, di, fmaf(sv.x, d2, bb.x));
    o.y = fmaf(acc.y, di, fmaf(sv.y, d2, bb.y));
    o.z = fmaf(acc.z, di, fmaf(sv.z, d2, bb.z));
    o.w = fmaf(acc.w, di, fmaf(sv.w, d2, bb.w));
    ((float4*)(out + (size_t)warp * DCAT))[lane] = o;
}

// ---------------------------------------------------------------------------
// Final linear: labels[N,16] = h[N,512] @ W_lin[512,16] + b_lin
// ---------------------------------------------------------------------------
__global__ void k_lin(const float* __restrict__ h, const float* __restrict__ Wl,
                      const float* __restrict__ bl, float* __restrict__ out) {
    __shared__ float ws[DCAT * 17];
    __shared__ float bs[NCLS];
    for (int idx = threadIdx.x; idx < DCAT * NCLS; idx += blockDim.x) {
        int c = idx >> 4;
        int k = idx & 15;
        ws[c * 17 + k] = Wl[idx];
    }
    if (threadIdx.x < NCLS) bs[threadIdx.x] = bl[threadIdx.x];
    __syncthreads();

    int warp = threadIdx.x >> 5;
    int lane = threadIdx.x & 31;
    int warpsPerGrid = (blockDim.x >> 5) * gridDim.x;
    for (int node = blockIdx.x * (blockDim.x >> 5) + warp; node < N_NODES;
         node += warpsPerGrid) {
        float acc[NCLS];
#pragma unroll
        for (int k = 0; k < NCLS; ++k) acc[k] = 0.0f;
        const float* hr = h + (size_t)node * DCAT;
#pragma unroll
        for (int j = 0; j < DCAT / 32; ++j) {
            int cidx = lane + 32 * j;
            float hv = hr[cidx];
            const float* wrow = &ws[cidx * 17];
#pragma unroll
            for (int k = 0; k < NCLS; ++k)
                acc[k] = fmaf(hv, wrow[k], acc[k]);
        }
#pragma unroll
        for (int off = 16; off > 0; off >>= 1) {
#pragma unroll
            for (int k = 0; k < NCLS; ++k)
                acc[k] += __shfl_xor_sync(0xffffffffu, acc[k], off);
        }
        if (lane == 0) {
            float* op = out + (size_t)node * NCLS;
#pragma unroll
            for (int k = 0; k < NCLS; ++k) op[k] = acc[k] + bs[k];
        }
    }
}

// ---------------------------------------------------------------------------
extern "C" void kernel_launch(void* const* d_in, const int* in_sizes, int n_in,
                              void* d_out, int out_size) {
    const float* x     = (const float*)d_in[0];
    const int*   ei    = (const int*)d_in[1];      // int32 (JAX x64 off)
    const float* W[3]  = {(const float*)d_in[2], (const float*)d_in[4],
                          (const float*)d_in[6]};
    const float* b[3]  = {(const float*)d_in[3], (const float*)d_in[5],
                          (const float*)d_in[7]};
    const float* W_lin = (const float*)d_in[8];
    const float* b_lin = (const float*)d_in[9];

    float* labels = (float*)d_out;                      // [N, 16]
    float* h      = labels + (size_t)N_NODES * NCLS;    // [N, 512]

    const int TB = 256;
    k_init <<<(N_NODES * 32 + TB - 1) / TB, TB>>>(x, h);
    k_deg  <<<(N_EDGES + TB - 1) / TB, TB>>>(ei);
    k_scan <<<1, 1024>>>();
    k_rsqrt<<<(N_NODES + TB - 1) / TB, TB>>>();
    k_fill <<<(N_EDGES + TB - 1) / TB, TB>>>(ei);

    for (int l = 0; l < 3; ++l) {
        const float* in  = h + l * C;          // stride DCAT
        float*       out = h + (l + 1) * C;    // stride DCAT
        k_gemm<<<(N_NODES + 127) / 128, 256>>>(in, W[l]);
        k_aggr<<<(N_NODES * 32 + TB - 1) / TB, TB>>>(b[l], out);
    }

    k_lin<<<2048, 256>>>(h, W_lin, b_lin, labels);
}

// round 5
// speedup vs baseline: 1.3157x; 1.1967x over previous
#include <cuda_runtime.h>
#include <cuda_bf16.h>

#define N_NODES 100000
#define N_EDGES 1600000
#define C       128
#define NCLS    16
#define DCAT    512   // 128 + 3*128

// ---- scratch (device globals: no allocation allowed) ----
__device__ float g_tmp[(size_t)N_NODES * C];   // x_prev @ W  (51.2 MB)
__device__ float g_dis[N_NODES];               // rsqrt(degree)
__device__ int   g_cnt[N_NODES];               // in-degree counts
__device__ int   g_rowstart[N_NODES + 1];      // CSR row offsets
__device__ int   g_cursor[N_NODES];            // fill cursors
__device__ int   g_csr_src[N_EDGES];           // CSR: src node per slot
__device__ float g_csr_w[N_EDGES];             // CSR: dis[src] per slot
__device__ __nv_bfloat16 g_Wt_hi[C * C];       // W transposed [n][k], hi part
__device__ __nv_bfloat16 g_Wt_lo[C * C];       // W transposed [n][k], lo part

// ---------------------------------------------------------------------------
// K0: copy x into h[:,0:128] (stride 512); zero degree counters.
// ---------------------------------------------------------------------------
__global__ void k_init(const float* __restrict__ x, float* __restrict__ h) {
    int t = blockIdx.x * blockDim.x + threadIdx.x;
    if (t >= N_NODES * 32) return;
    int node = t >> 5;
    int lane = t & 31;
    float4 v = ((const float4*)(x + (size_t)node * C))[lane];
    ((float4*)(h + (size_t)node * DCAT))[lane] = v;
    if (lane == 0) g_cnt[node] = 0;
}

// K1: in-degree count. edge_index is int32: row0 = src, row1 = dst.
__global__ void k_deg(const int* __restrict__ ei) {
    int e = blockIdx.x * blockDim.x + threadIdx.x;
    if (e >= N_EDGES) return;
    int d = ei[N_EDGES + e];
    atomicAdd(&g_cnt[d], 1);
}

// K2: single-block exclusive scan of g_cnt -> g_rowstart / g_cursor
__global__ void k_scan() {
    __shared__ int buf[1024];
    __shared__ int carry;
    int tid = threadIdx.x;
    if (tid == 0) carry = 0;
    __syncthreads();
    for (int base = 0; base < N_NODES; base += 1024) {
        int i = base + tid;
        int v = (i < N_NODES) ? g_cnt[i] : 0;
        buf[tid] = v;
        __syncthreads();
        for (int off = 1; off < 1024; off <<= 1) {
            int t = (tid >= off) ? buf[tid - off] : 0;
            __syncthreads();
            buf[tid] += t;
            __syncthreads();
        }
        int incl = buf[tid];
        int oldc = carry;
        if (i < N_NODES) {
            int excl = oldc + incl - v;
            g_rowstart[i] = excl;
            g_cursor[i]   = excl;
        }
        __syncthreads();
        if (tid == 1023) carry = oldc + incl;
        __syncthreads();
    }
    if (threadIdx.x == 0) g_rowstart[N_NODES] = carry;
}

// K3: dis = rsqrt(indeg + 1)   (+1 = self loop)
__global__ void k_rsqrt() {
    int i = blockIdx.x * blockDim.x + threadIdx.x;
    if (i < N_NODES) g_dis[i] = rsqrtf((float)(g_cnt[i] + 1));
}

// K4: bucket-fill CSR
__global__ void k_fill(const int* __restrict__ ei) {
    int e = blockIdx.x * blockDim.x + threadIdx.x;
    if (e >= N_EDGES) return;
    int s = ei[e];
    int d = ei[N_EDGES + e];
    int pos = atomicAdd(&g_cursor[d], 1);
    g_csr_src[pos] = s;
    g_csr_w[pos]   = g_dis[s];
}

// ---------------------------------------------------------------------------
// K5: convert W[k][n] fp32 -> transposed [n][k] bf16 hi/lo split
// ---------------------------------------------------------------------------
__global__ void k_wconv(const float* __restrict__ W) {
    int idx = blockIdx.x * blockDim.x + threadIdx.x;
    if (idx >= C * C) return;
    int k = idx >> 7;
    int n = idx & 127;
    float v = W[idx];
    __nv_bfloat16 hi = __float2bfloat16_rn(v);
    float lo = v - __bfloat162float(hi);
    g_Wt_hi[n * C + k] = hi;
    g_Wt_lo[n * C + k] = __float2bfloat16_rn(lo);
}

// ---------------------------------------------------------------------------
// GEMM (tensor-core, bf16 split): g_tmp[N,128] = in[N, stride DCAT] @ W
// acc = hi@Whi + lo@Whi + hi@Wlo  (fp32 accumulate; lo@Wlo dropped, ~2^-18)
// 256 threads = 8 warps; block tile 128x128; warp tile 64x32 (m16n8k16).
// Smem stride 40 elems -> conflict-free frag loads.
// ---------------------------------------------------------------------------
#define APAD 40
__device__ __forceinline__ void mma_bf16(float c[4], const unsigned a[4],
                                         const unsigned b[2]) {
    asm volatile(
        "mma.sync.aligned.m16n8k16.row.col.f32.bf16.bf16.f32 "
        "{%0,%1,%2,%3}, {%4,%5,%6,%7}, {%8,%9}, {%0,%1,%2,%3};\n"
        : "+f"(c[0]), "+f"(c[1]), "+f"(c[2]), "+f"(c[3])
        : "r"(a[0]), "r"(a[1]), "r"(a[2]), "r"(a[3]), "r"(b[0]), "r"(b[1]));
}

__global__ void __launch_bounds__(256)
k_gemm_tc(const float* __restrict__ in) {
    __shared__ __nv_bfloat16 a_hi[128][APAD];
    __shared__ __nv_bfloat16 a_lo[128][APAD];
    __shared__ __nv_bfloat16 b_hi[128][APAD];
    __shared__ __nv_bfloat16 b_lo[128][APAD];

    int tid  = threadIdx.x;
    int lane = tid & 31;
    int wid  = tid >> 5;
    int wm   = wid & 1;        // warp row group (0..1) -> 64 rows
    int wn   = wid >> 1;       // warp col group (0..3) -> 32 cols
    int row0 = blockIdx.x * 128;

    // staging indices
    int arow = tid >> 1;               // 0..127
    int akb  = (tid & 1) * 16;         // 0 / 16 within 32-k chunk
    int grow = row0 + arow;
    if (grow >= N_NODES) grow = N_NODES - 1;
    const float* aptr = in + (size_t)grow * DCAT;

    int bcol = tid >> 1;               // 0..127 (output col)
    int bkb  = (tid & 1) * 16;

    float acc[4][4][4];
#pragma unroll
    for (int i = 0; i < 4; ++i)
#pragma unroll
        for (int j = 0; j < 4; ++j)
#pragma unroll
            for (int q = 0; q < 4; ++q) acc[i][j][q] = 0.0f;

    for (int k0 = 0; k0 < C; k0 += 32) {
        // ---- fetch gmem ----
        float av[16];
#pragma unroll
        for (int j = 0; j < 4; ++j) {
            float4 v = *(const float4*)(aptr + k0 + akb + j * 4);
            av[j * 4 + 0] = v.x; av[j * 4 + 1] = v.y;
            av[j * 4 + 2] = v.z; av[j * 4 + 3] = v.w;
        }
        uint4 wv_hi0 = *(const uint4*)(&g_Wt_hi[bcol * C + k0 + bkb]);
        uint4 wv_hi1 = *(const uint4*)(&g_Wt_hi[bcol * C + k0 + bkb + 8]);
        uint4 wv_lo0 = *(const uint4*)(&g_Wt_lo[bcol * C + k0 + bkb]);
        uint4 wv_lo1 = *(const uint4*)(&g_Wt_lo[bcol * C + k0 + bkb + 8]);

        // ---- convert A ----
        unsigned ah[8], al[8];
#pragma unroll
        for (int j = 0; j < 8; ++j) {
            float v0 = av[2 * j], v1 = av[2 * j + 1];
            __nv_bfloat16 h0 = __float2bfloat16_rn(v0);
            __nv_bfloat16 h1 = __float2bfloat16_rn(v1);
            float l0 = v0 - __bfloat162float(h0);
            float l1 = v1 - __bfloat162float(h1);
            __nv_bfloat162 hp = __halves2bfloat162(h0, h1);
            __nv_bfloat162 lp = __halves2bfloat162(__float2bfloat16_rn(l0),
                                                   __float2bfloat16_rn(l1));
            ah[j] = *(unsigned*)&hp;
            al[j] = *(unsigned*)&lp;
        }

        __syncthreads();   // previous chunk fully consumed
        *(uint4*)&a_hi[arow][akb]     = make_uint4(ah[0], ah[1], ah[2], ah[3]);
        *(uint4*)&a_hi[arow][akb + 8] = make_uint4(ah[4], ah[5], ah[6], ah[7]);
        *(uint4*)&a_lo[arow][akb]     = make_uint4(al[0], al[1], al[2], al[3]);
        *(uint4*)&a_lo[arow][akb + 8] = make_uint4(al[4], al[5], al[6], al[7]);
        *(uint4*)&b_hi[bcol][bkb]     = wv_hi0;
        *(uint4*)&b_hi[bcol][bkb + 8] = wv_hi1;
        *(uint4*)&b_lo[bcol][bkb]     = wv_lo0;
        *(uint4*)&b_lo[bcol][bkb + 8] = wv_lo1;
        __syncthreads();

        // ---- mma over 2 k16 steps ----
#pragma unroll
        for (int ks = 0; ks < 2; ++ks) {
            int kb = ks * 16 + (lane & 3) * 2;
            unsigned bh[4][2], bl[4][2];
#pragma unroll
            for (int ni = 0; ni < 4; ++ni) {
                int col = wn * 32 + ni * 8 + (lane >> 2);
                bh[ni][0] = *(unsigned*)&b_hi[col][kb];
                bh[ni][1] = *(unsigned*)&b_hi[col][kb + 8];
                bl[ni][0] = *(unsigned*)&b_lo[col][kb];
                bl[ni][1] = *(unsigned*)&b_lo[col][kb + 8];
            }
#pragma unroll
            for (int mi = 0; mi < 4; ++mi) {
                int r = wm * 64 + mi * 16 + (lane >> 2);
                unsigned AH[4], AL[4];
                AH[0] = *(unsigned*)&a_hi[r][kb];
                AH[1] = *(unsigned*)&a_hi[r + 8][kb];
                AH[2] = *(unsigned*)&a_hi[r][kb + 8];
                AH[3] = *(unsigned*)&a_hi[r + 8][kb + 8];
                AL[0] = *(unsigned*)&a_lo[r][kb];
                AL[1] = *(unsigned*)&a_lo[r + 8][kb];
                AL[2] = *(unsigned*)&a_lo[r][kb + 8];
                AL[3] = *(unsigned*)&a_lo[r + 8][kb + 8];
#pragma unroll
                for (int ni = 0; ni < 4; ++ni) {
                    mma_bf16(acc[mi][ni], AH, bh[ni]);
                    mma_bf16(acc[mi][ni], AL, bh[ni]);
                    mma_bf16(acc[mi][ni], AH, bl[ni]);
                }
            }
        }
    }

    // ---- store ----
#pragma unroll
    for (int mi = 0; mi < 4; ++mi) {
        int r = row0 + wm * 64 + mi * 16 + (lane >> 2);
#pragma unroll
        for (int ni = 0; ni < 4; ++ni) {
            int col = wn * 32 + ni * 8 + (lane & 3) * 2;
            if (r < N_NODES) {
                float2 v0 = make_float2(acc[mi][ni][0], acc[mi][ni][1]);
                *(float2*)(g_tmp + (size_t)r * C + col) = v0;
            }
            if (r + 8 < N_NODES) {
                float2 v1 = make_float2(acc[mi][ni][2], acc[mi][ni][3]);
                *(float2*)(g_tmp + (size_t)(r + 8) * C + col) = v1;
            }
        }
    }
}

// ---------------------------------------------------------------------------
// Aggregation: one warp per node; gather-only, no atomics.
// out[d] = dis[d]*sum(dis[s]*tmp[s]) + dis[d]^2*tmp[d] + b
// ---------------------------------------------------------------------------
__global__ void k_aggr(const float* __restrict__ b, float* __restrict__ out) {
    int warp = (blockIdx.x * blockDim.x + threadIdx.x) >> 5;
    int lane = threadIdx.x & 31;
    if (warp >= N_NODES) return;

    int rs = g_rowstart[warp];
    int re = g_rowstart[warp + 1];
    float4 acc = make_float4(0.f, 0.f, 0.f, 0.f);

#pragma unroll 4
    for (int e = rs; e < re; ++e) {
        int   s = g_csr_src[e];
        float w = g_csr_w[e];
        float4 v = ((const float4*)(g_tmp + (size_t)s * C))[lane];
        acc.x = fmaf(v.x, w, acc.x);
        acc.y = fmaf(v.y, w, acc.y);
        acc.z = fmaf(v.z, w, acc.z);
        acc.w = fmaf(v.w, w, acc.w);
    }

    float di = g_dis[warp];
    float d2 = di * di;
    float4 sv = ((const float4*)(g_tmp + (size_t)warp * C))[lane];
    float4 bb = ((const float4*)b)[lane];
    float4 o;
    o.x = fmaf(acc.x, di, fmaf(sv.x, d2, bb.x));
    o.y = fmaf(acc.y, di, fmaf(sv.y, d2, bb.y));
    o.z = fmaf(acc.z, di, fmaf(sv.z, d2, bb.z));
    o.w = fmaf(acc.w, di, fmaf(sv.w, d2, bb.w));
    ((float4*)(out + (size_t)warp * DCAT))[lane] = o;
}

// ---------------------------------------------------------------------------
// Final linear: labels[N,16] = h[N,512] @ W_lin[512,16] + b_lin
// ---------------------------------------------------------------------------
__global__ void k_lin(const float* __restrict__ h, const float* __restrict__ Wl,
                      const float* __restrict__ bl, float* __restrict__ out) {
    __shared__ float ws[DCAT * 17];
    __shared__ float bs[NCLS];
    for (int idx = threadIdx.x; idx < DCAT * NCLS; idx += blockDim.x) {
        int c = idx >> 4;
        int k = idx & 15;
        ws[c * 17 + k] = Wl[idx];
    }
    if (threadIdx.x < NCLS) bs[threadIdx.x] = bl[threadIdx.x];
    __syncthreads();

    int warp = threadIdx.x >> 5;
    int lane = threadIdx.x & 31;
    int warpsPerGrid = (blockDim.x >> 5) * gridDim.x;
    for (int node = blockIdx.x * (blockDim.x >> 5) + warp; node < N_NODES;
         node += warpsPerGrid) {
        float acc[NCLS];
#pragma unroll
        for (int k = 0; k < NCLS; ++k) acc[k] = 0.0f;
        const float* hr = h + (size_t)node * DCAT;
#pragma unroll
        for (int j = 0; j < DCAT / 32; ++j) {
            int cidx = lane + 32 * j;
            float hv = hr[cidx];
            const float* wrow = &ws[cidx * 17];
#pragma unroll
            for (int k = 0; k < NCLS; ++k)
                acc[k] = fmaf(hv, wrow[k], acc[k]);
        }
#pragma unroll
        for (int off = 16; off > 0; off >>= 1) {
#pragma unroll
            for (int k = 0; k < NCLS; ++k)
                acc[k] += __shfl_xor_sync(0xffffffffu, acc[k], off);
        }
        if (lane == 0) {
            float* op = out + (size_t)node * NCLS;
#pragma unroll
            for (int k = 0; k < NCLS; ++k) op[k] = acc[k] + bs[k];
        }
    }
}

// ---------------------------------------------------------------------------
extern "C" void kernel_launch(void* const* d_in, const int* in_sizes, int n_in,
                              void* d_out, int out_size) {
    const float* x     = (const float*)d_in[0];
    const int*   ei    = (const int*)d_in[1];      // int32 (JAX x64 off)
    const float* W[3]  = {(const float*)d_in[2], (const float*)d_in[4],
                          (const float*)d_in[6]};
    const float* b[3]  = {(const float*)d_in[3], (const float*)d_in[5],
                          (const float*)d_in[7]};
    const float* W_lin = (const float*)d_in[8];
    const float* b_lin = (const float*)d_in[9];

    float* labels = (float*)d_out;                      // [N, 16]
    float* h      = labels + (size_t)N_NODES * NCLS;    // [N, 512]

    const int TB = 256;
    k_init <<<(N_NODES * 32 + TB - 1) / TB, TB>>>(x, h);
    k_deg  <<<(N_EDGES + TB - 1) / TB, TB>>>(ei);
    k_scan <<<1, 1024>>>();
    k_rsqrt<<<(N_NODES + TB - 1) / TB, TB>>>();
    k_fill <<<(N_EDGES + TB - 1) / TB, TB>>>(ei);

    for (int l = 0; l < 3; ++l) {
        const float* in  = h + l * C;          // stride DCAT
        float*       out = h + (l + 1) * C;    // stride DCAT
        k_wconv  <<<(C * C + TB - 1) / TB, TB>>>(W[l]);
        k_gemm_tc<<<(N_NODES + 127) / 128, 256>>>(in);
        k_aggr   <<<(N_NODES * 32 + TB - 1) / TB, TB>>>(b[l], out);
    }

    k_lin<<<2048, 256>>>(h, W_lin, b_lin, labels);
}

// round 6
// speedup vs baseline: 1.5890x; 1.2077x over previous
#include <cuda_runtime.h>
#include <cuda_bf16.h>

#define N_NODES 100000
#define N_EDGES 1600000
#define C       128
#define NCLS    16
#define DCAT    512   // 128 + 3*128
#define SB      1024
#define NB      ((N_NODES + SB - 1) / SB)   // 98 scan blocks

// ---- scratch (device globals: no allocation allowed) ----
__device__ float g_tmp[(size_t)N_NODES * C];   // x_prev @ W  (51.2 MB)
__device__ float g_dis[N_NODES];               // rsqrt(degree)
__device__ int   g_cnt[N_NODES];               // in-degree counts
__device__ int   g_rowstart[N_NODES + 1];      // CSR row offsets
__device__ int   g_cursor[N_NODES];            // fill cursors
__device__ int   g_bsum[NB];                   // scan block sums
__device__ int   g_boff[NB];                   // scan block offsets
__device__ int   g_csr_src[N_EDGES];           // CSR: src node per slot
__device__ float g_csr_w[N_EDGES];             // CSR: dis[src] per slot
__device__ __nv_bfloat16 g_Wt_hi[3][C * C];    // W^T [n][k] hi, per layer
__device__ __nv_bfloat16 g_Wt_lo[3][C * C];    // W^T [n][k] lo, per layer

// ---------------------------------------------------------------------------
// K0: copy x into h[:,0:128] (stride 512); zero degree counters.
// ---------------------------------------------------------------------------
__global__ void k_init(const float* __restrict__ x, float* __restrict__ h) {
    int t = blockIdx.x * blockDim.x + threadIdx.x;
    if (t >= N_NODES * 32) return;
    int node = t >> 5;
    int lane = t & 31;
    float4 v = ((const float4*)(x + (size_t)node * C))[lane];
    ((float4*)(h + (size_t)node * DCAT))[lane] = v;
    if (lane == 0) g_cnt[node] = 0;
}

// K1: convert all three W[k][n] fp32 -> transposed [n][k] bf16 hi/lo
__global__ void k_wconv(const float* __restrict__ W0,
                        const float* __restrict__ W1,
                        const float* __restrict__ W2) {
    int idx = blockIdx.x * blockDim.x + threadIdx.x;
    if (idx >= 3 * C * C) return;
    int l = idx / (C * C);
    int r = idx - l * (C * C);
    const float* W = (l == 0) ? W0 : (l == 1) ? W1 : W2;
    int k = r >> 7;
    int n = r & 127;
    float v = W[r];
    __nv_bfloat16 hi = __float2bfloat16_rn(v);
    float lo = v - __bfloat162float(hi);
    g_Wt_hi[l][n * C + k] = hi;
    g_Wt_lo[l][n * C + k] = __float2bfloat16_rn(lo);
}

// K2: in-degree count. edge_index is int32: row0 = src, row1 = dst.
__global__ void k_deg(const int* __restrict__ ei) {
    int e = blockIdx.x * blockDim.x + threadIdx.x;
    if (e >= N_EDGES) return;
    atomicAdd(&g_cnt[ei[N_EDGES + e]], 1);
}

// ---------------------------------------------------------------------------
// Multi-block scan: A) per-block exclusive scan + block sums
//                   B) scan block sums   C) add offsets, finalize + rsqrt
// ---------------------------------------------------------------------------
__global__ void k_scanA() {
    int i = blockIdx.x * SB + threadIdx.x;
    int lane = threadIdx.x & 31, wid = threadIdx.x >> 5;
    int v = (i < N_NODES) ? g_cnt[i] : 0;
    int s = v;
#pragma unroll
    for (int o = 1; o < 32; o <<= 1) {
        int t = __shfl_up_sync(0xffffffffu, s, o);
        if (lane >= o) s += t;
    }
    __shared__ int wsum[32];
    if (lane == 31) wsum[wid] = s;
    __syncthreads();
    if (wid == 0) {
        int t = wsum[lane];
#pragma unroll
        for (int o = 1; o < 32; o <<= 1) {
            int u = __shfl_up_sync(0xffffffffu, t, o);
            if (lane >= o) t += u;
        }
        wsum[lane] = t;
    }
    __syncthreads();
    int incl = s + (wid > 0 ? wsum[wid - 1] : 0);
    if (i < N_NODES) g_rowstart[i] = incl - v;   // exclusive within block
    if (threadIdx.x == SB - 1) g_bsum[blockIdx.x] = incl;
}

__global__ void k_scanB() {       // one block, 128 threads (NB=98 <= 128)
    int tid = threadIdx.x;
    int lane = tid & 31, wid = tid >> 5;
    int v = (tid < NB) ? g_bsum[tid] : 0;
    int s = v;
#pragma unroll
    for (int o = 1; o < 32; o <<= 1) {
        int t = __shfl_up_sync(0xffffffffu, s, o);
        if (lane >= o) s += t;
    }
    __shared__ int wsum[4];
    if (lane == 31) wsum[wid] = s;
    __syncthreads();
    int woff = 0;
    for (int w = 0; w < wid; ++w) woff += wsum[w];
    int incl = s + woff;
    if (tid < NB) g_boff[tid] = incl - v;
    if (tid == NB - 1) g_rowstart[N_NODES] = incl;
}

__global__ void k_scanC() {
    int i = blockIdx.x * blockDim.x + threadIdx.x;
    if (i >= N_NODES) return;
    int e = g_rowstart[i] + g_boff[i >> 10];
    g_rowstart[i] = e;
    g_cursor[i]   = e;
    g_dis[i]      = rsqrtf((float)(g_cnt[i] + 1));
}

// K: bucket-fill CSR
__global__ void k_fill(const int* __restrict__ ei) {
    int e = blockIdx.x * blockDim.x + threadIdx.x;
    if (e >= N_EDGES) return;
    int s = ei[e];
    int d = ei[N_EDGES + e];
    int pos = atomicAdd(&g_cursor[d], 1);
    g_csr_src[pos] = s;
    g_csr_w[pos]   = g_dis[s];
}

// ---------------------------------------------------------------------------
// GEMM (tensor-core, bf16 split): g_tmp = in @ W
// acc = hi@Whi + lo@Whi + hi@Wlo  (fp32 accumulate)
// ---------------------------------------------------------------------------
#define APAD 40
__device__ __forceinline__ void mma_bf16(float c[4], const unsigned a[4],
                                         const unsigned b[2]) {
    asm volatile(
        "mma.sync.aligned.m16n8k16.row.col.f32.bf16.bf16.f32 "
        "{%0,%1,%2,%3}, {%4,%5,%6,%7}, {%8,%9}, {%0,%1,%2,%3};\n"
        : "+f"(c[0]), "+f"(c[1]), "+f"(c[2]), "+f"(c[3])
        : "r"(a[0]), "r"(a[1]), "r"(a[2]), "r"(a[3]), "r"(b[0]), "r"(b[1]));
}

__global__ void __launch_bounds__(256)
k_gemm_tc(const float* __restrict__ in, int layer) {
    __shared__ __nv_bfloat16 a_hi[128][APAD];
    __shared__ __nv_bfloat16 a_lo[128][APAD];
    __shared__ __nv_bfloat16 b_hi[128][APAD];
    __shared__ __nv_bfloat16 b_lo[128][APAD];

    const __nv_bfloat16* Whi = g_Wt_hi[layer];
    const __nv_bfloat16* Wlo = g_Wt_lo[layer];

    int tid  = threadIdx.x;
    int lane = tid & 31;
    int wid  = tid >> 5;
    int wm   = wid & 1;
    int wn   = wid >> 1;
    int row0 = blockIdx.x * 128;

    int arow = tid >> 1;
    int akb  = (tid & 1) * 16;
    int grow = row0 + arow;
    if (grow >= N_NODES) grow = N_NODES - 1;
    const float* aptr = in + (size_t)grow * DCAT;

    int bcol = tid >> 1;
    int bkb  = (tid & 1) * 16;

    float acc[4][4][4];
#pragma unroll
    for (int i = 0; i < 4; ++i)
#pragma unroll
        for (int j = 0; j < 4; ++j)
#pragma unroll
            for (int q = 0; q < 4; ++q) acc[i][j][q] = 0.0f;

    for (int k0 = 0; k0 < C; k0 += 32) {
        float av[16];
#pragma unroll
        for (int j = 0; j < 4; ++j) {
            float4 v = *(const float4*)(aptr + k0 + akb + j * 4);
            av[j * 4 + 0] = v.x; av[j * 4 + 1] = v.y;
            av[j * 4 + 2] = v.z; av[j * 4 + 3] = v.w;
        }
        uint4 wv_hi0 = *(const uint4*)(&Whi[bcol * C + k0 + bkb]);
        uint4 wv_hi1 = *(const uint4*)(&Whi[bcol * C + k0 + bkb + 8]);
        uint4 wv_lo0 = *(const uint4*)(&Wlo[bcol * C + k0 + bkb]);
        uint4 wv_lo1 = *(const uint4*)(&Wlo[bcol * C + k0 + bkb + 8]);

        unsigned ah[8], al[8];
#pragma unroll
        for (int j = 0; j < 8; ++j) {
            float v0 = av[2 * j], v1 = av[2 * j + 1];
            __nv_bfloat16 h0 = __float2bfloat16_rn(v0);
            __nv_bfloat16 h1 = __float2bfloat16_rn(v1);
            float l0 = v0 - __bfloat162float(h0);
            float l1 = v1 - __bfloat162float(h1);
            __nv_bfloat162 hp = __halves2bfloat162(h0, h1);
            __nv_bfloat162 lp = __halves2bfloat162(__float2bfloat16_rn(l0),
                                                   __float2bfloat16_rn(l1));
            ah[j] = *(unsigned*)&hp;
            al[j] = *(unsigned*)&lp;
        }

        __syncthreads();
        *(uint4*)&a_hi[arow][akb]     = make_uint4(ah[0], ah[1], ah[2], ah[3]);
        *(uint4*)&a_hi[arow][akb + 8] = make_uint4(ah[4], ah[5], ah[6], ah[7]);
        *(uint4*)&a_lo[arow][akb]     = make_uint4(al[0], al[1], al[2], al[3]);
        *(uint4*)&a_lo[arow][akb + 8] = make_uint4(al[4], al[5], al[6], al[7]);
        *(uint4*)&b_hi[bcol][bkb]     = wv_hi0;
        *(uint4*)&b_hi[bcol][bkb + 8] = wv_hi1;
        *(uint4*)&b_lo[bcol][bkb]     = wv_lo0;
        *(uint4*)&b_lo[bcol][bkb + 8] = wv_lo1;
        __syncthreads();

#pragma unroll
        for (int ks = 0; ks < 2; ++ks) {
            int kb = ks * 16 + (lane & 3) * 2;
            unsigned bh[4][2], bl[4][2];
#pragma unroll
            for (int ni = 0; ni < 4; ++ni) {
                int col = wn * 32 + ni * 8 + (lane >> 2);
                bh[ni][0] = *(unsigned*)&b_hi[col][kb];
                bh[ni][1] = *(unsigned*)&b_hi[col][kb + 8];
                bl[ni][0] = *(unsigned*)&b_lo[col][kb];
                bl[ni][1] = *(unsigned*)&b_lo[col][kb + 8];
            }
#pragma unroll
            for (int mi = 0; mi < 4; ++mi) {
                int r = wm * 64 + mi * 16 + (lane >> 2);
                unsigned AH[4], AL[4];
                AH[0] = *(unsigned*)&a_hi[r][kb];
                AH[1] = *(unsigned*)&a_hi[r + 8][kb];
                AH[2] = *(unsigned*)&a_hi[r][kb + 8];
                AH[3] = *(unsigned*)&a_hi[r + 8][kb + 8];
                AL[0] = *(unsigned*)&a_lo[r][kb];
                AL[1] = *(unsigned*)&a_lo[r + 8][kb];
                AL[2] = *(unsigned*)&a_lo[r][kb + 8];
                AL[3] = *(unsigned*)&a_lo[r + 8][kb + 8];
#pragma unroll
                for (int ni = 0; ni < 4; ++ni) {
                    mma_bf16(acc[mi][ni], AH, bh[ni]);
                    mma_bf16(acc[mi][ni], AL, bh[ni]);
                    mma_bf16(acc[mi][ni], AH, bl[ni]);
                }
            }
        }
    }

#pragma unroll
    for (int mi = 0; mi < 4; ++mi) {
        int r = row0 + wm * 64 + mi * 16 + (lane >> 2);
#pragma unroll
        for (int ni = 0; ni < 4; ++ni) {
            int col = wn * 32 + ni * 8 + (lane & 3) * 2;
            if (r < N_NODES) {
                *(float2*)(g_tmp + (size_t)r * C + col) =
                    make_float2(acc[mi][ni][0], acc[mi][ni][1]);
            }
            if (r + 8 < N_NODES) {
                *(float2*)(g_tmp + (size_t)(r + 8) * C + col) =
                    make_float2(acc[mi][ni][2], acc[mi][ni][3]);
            }
        }
    }
}

// ---------------------------------------------------------------------------
// Aggregation: one warp per node; gather-only, no atomics.
// ---------------------------------------------------------------------------
__global__ void k_aggr(const float* __restrict__ b, float* __restrict__ out) {
    int warp = (blockIdx.x * blockDim.x + threadIdx.x) >> 5;
    int lane = threadIdx.x & 31;
    if (warp >= N_NODES) return;

    int rs = g_rowstart[warp];
    int re = g_rowstart[warp + 1];
    float4 acc = make_float4(0.f, 0.f, 0.f, 0.f);

#pragma unroll 4
    for (int e = rs; e < re; ++e) {
        int   s = g_csr_src[e];
        float w = g_csr_w[e];
        float4 v = ((const float4*)(g_tmp + (size_t)s * C))[lane];
        acc.x = fmaf(v.x, w, acc.x);
        acc.y = fmaf(v.y, w, acc.y);
        acc.z = fmaf(v.z, w, acc.z);
        acc.w = fmaf(v.w, w, acc.w);
    }

    float di = g_dis[warp];
    float d2 = di * di;
    float4 sv = ((const float4*)(g_tmp + (size_t)warp * C))[lane];
    float4 bb = ((const float4*)b)[lane];
    float4 o;
    o.x = fmaf(acc.x, di, fmaf(sv.x, d2, bb.x));
    o.y = fmaf(acc.y, di, fmaf(sv.y, d2, bb.y));
    o.z = fmaf(acc.z, di, fmaf(sv.z, d2, bb.z));
    o.w = fmaf(acc.w, di, fmaf(sv.w, d2, bb.w));
    ((float4*)(out + (size_t)warp * DCAT))[lane] = o;
}

// ---------------------------------------------------------------------------
// Final linear: labels[N,16] = h[N,512] @ W_lin[512,16] + b_lin
// ---------------------------------------------------------------------------
__global__ void k_lin(const float* __restrict__ h, const float* __restrict__ Wl,
                      const float* __restrict__ bl, float* __restrict__ out) {
    __shared__ float ws[DCAT * 17];
    __shared__ float bs[NCLS];
    for (int idx = threadIdx.x; idx < DCAT * NCLS; idx += blockDim.x) {
        int c = idx >> 4;
        int k = idx & 15;
        ws[c * 17 + k] = Wl[idx];
    }
    if (threadIdx.x < NCLS) bs[threadIdx.x] = bl[threadIdx.x];
    __syncthreads();

    int warp = threadIdx.x >> 5;
    int lane = threadIdx.x & 31;
    int warpsPerGrid = (blockDim.x >> 5) * gridDim.x;
    for (int node = blockIdx.x * (blockDim.x >> 5) + warp; node < N_NODES;
         node += warpsPerGrid) {
        float acc[NCLS];
#pragma unroll
        for (int k = 0; k < NCLS; ++k) acc[k] = 0.0f;
        const float* hr = h + (size_t)node * DCAT;
#pragma unroll
        for (int j = 0; j < 4; ++j) {
            int cidx = j * 128 + lane * 4;
            float4 hv = *(const float4*)(hr + cidx);
            const float* w0 = &ws[(cidx + 0) * 17];
            const float* w1 = &ws[(cidx + 1) * 17];
            const float* w2 = &ws[(cidx + 2) * 17];
            const float* w3 = &ws[(cidx + 3) * 17];
#pragma unroll
            for (int k = 0; k < NCLS; ++k)
                acc[k] = fmaf(hv.x, w0[k], fmaf(hv.y, w1[k],
                         fmaf(hv.z, w2[k], fmaf(hv.w, w3[k], acc[k]))));
        }
#pragma unroll
        for (int off = 16; off > 0; off >>= 1) {
#pragma unroll
            for (int k = 0; k < NCLS; ++k)
                acc[k] += __shfl_xor_sync(0xffffffffu, acc[k], off);
        }
        if (lane == 0) {
            float* op = out + (size_t)node * NCLS;
#pragma unroll
            for (int k = 0; k < NCLS; ++k) op[k] = acc[k] + bs[k];
        }
    }
}

// ---------------------------------------------------------------------------
extern "C" void kernel_launch(void* const* d_in, const int* in_sizes, int n_in,
                              void* d_out, int out_size) {
    const float* x     = (const float*)d_in[0];
    const int*   ei    = (const int*)d_in[1];      // int32 (JAX x64 off)
    const float* W1    = (const float*)d_in[2];
    const float* b1    = (const float*)d_in[3];
    const float* W2    = (const float*)d_in[4];
    const float* b2    = (const float*)d_in[5];
    const float* W3    = (const float*)d_in[6];
    const float* b3    = (const float*)d_in[7];
    const float* W_lin = (const float*)d_in[8];
    const float* b_lin = (const float*)d_in[9];
    const float* bias[3] = {b1, b2, b3};

    float* labels = (float*)d_out;                      // [N, 16]
    float* h      = labels + (size_t)N_NODES * NCLS;    // [N, 512]

    const int TB = 256;
    // Order chosen so the ncu -s window lands on k_gemm_tc (4th launch).
    k_init <<<(N_NODES * 32 + TB - 1) / TB, TB>>>(x, h);
    k_wconv<<<(3 * C * C + TB - 1) / TB, TB>>>(W1, W2, W3);
    k_deg  <<<(N_EDGES + TB - 1) / TB, TB>>>(ei);
    k_gemm_tc<<<(N_NODES + 127) / 128, 256>>>(h, 0);   // layer 1 GEMM
    k_scanA<<<NB, SB>>>();
    k_scanB<<<1, 128>>>();
    k_scanC<<<(N_NODES + TB - 1) / TB, TB>>>();
    k_fill <<<(N_EDGES + TB - 1) / TB, TB>>>(ei);

    k_aggr<<<(N_NODES * 32 + TB - 1) / TB, TB>>>(bias[0], h + 1 * C);
    for (int l = 1; l < 3; ++l) {
        k_gemm_tc<<<(N_NODES + 127) / 128, 256>>>(h + l * C, l);
        k_aggr<<<(N_NODES * 32 + TB - 1) / TB, TB>>>(bias[l], h + (l + 1) * C);
    }

    k_lin<<<2048, 256>>>(h, W_lin, b_lin, labels);
}